// round 12
// baseline (speedup 1.0000x reference)
#include <cuda_runtime.h>
#include <mma.h>
#include <math.h>

using namespace nvcuda;

#define D_MODEL 1024
#define NUM_HEADS 16
#define HEAD_DIM 64
#define SEQ 2048
#define MAX_BS 4096   // B*S for B=2

// Scratch (allocation-free rule: __device__ globals)
__device__ float g_Qp[MAX_BS * D_MODEL];
__device__ float g_Kp[MAX_BS * D_MODEL];
__device__ float g_Vp[MAX_BS * D_MODEL];
__device__ float g_AO[MAX_BS * D_MODEL];

// ----------------------------------------------------------------------------
// tf32 helpers (3xTF32: x = hi + lo, both tf32-representable)
// ----------------------------------------------------------------------------
__device__ __forceinline__ float tf32_rna(float x) {
    float r;
    asm("cvt.rna.tf32.f32 %0, %1;" : "=f"(r) : "f"(x));
    return r;
}
__device__ __forceinline__ void split1(float v, float& hi, float& lo) {
    hi = tf32_rna(v);
    lo = tf32_rna(v - hi);
}
__device__ __forceinline__ void split4(const float4 v, float4& hi, float4& lo) {
    split1(v.x, hi.x, lo.x);
    split1(v.y, hi.y, lo.y);
    split1(v.z, hi.z, lo.z);
    split1(v.w, hi.w, lo.w);
}

// ----------------------------------------------------------------------------
// Tensor-core GEMM + bias: C[M,1024] = A[M,1024] @ W[1024,1024] + bias
// 3xTF32 via wmma m16n16k8. BM=BN=128, BK=16, 256 threads = 8 warps.
// ----------------------------------------------------------------------------
#define LDA 20    // A smem leading dim ([m][k], k=16 padded to 20)
#define LDB 132   // B smem leading dim ([k][n], n=128 padded to 132)

__device__ __forceinline__ void gemm_bias_tc(
    const float* __restrict__ A, const float* __restrict__ W,
    const float* __restrict__ bias, float* __restrict__ C)
{
    __shared__ float sAh[128 * LDA];
    __shared__ float sAl[128 * LDA];
    __shared__ float sBh[16 * LDB];
    __shared__ float sBl[16 * LDB];
    __shared__ float sEp[8][16 * 20];

    const int tid  = threadIdx.x;
    const int warp = tid >> 5;
    const int lane = tid & 31;
    const int mbase = blockIdx.y * 128;
    const int nbase = blockIdx.x * 128;
    const int wm = (warp & 3) * 32;
    const int wn = (warp >> 2) * 64;

    const int aR0 = tid >> 2;
    const int aC  = (tid & 3) * 4;
    const int bR0 = tid >> 5;
    const int bC  = (tid & 31) * 4;

    const float* Ap = A + (size_t)(mbase + aR0) * D_MODEL + aC;
    const float* Wp = W + (size_t)bR0 * D_MODEL + nbase + bC;

    wmma::fragment<wmma::accumulator, 16, 16, 8, float> acc[2][4];
#pragma unroll
    for (int i = 0; i < 2; i++)
#pragma unroll
        for (int j = 0; j < 4; j++)
            wmma::fill_fragment(acc[i][j], 0.0f);

    float4 rA0 = *(const float4*)(Ap);
    float4 rA1 = *(const float4*)(Ap + (size_t)64 * D_MODEL);
    float4 rB0 = *(const float4*)(Wp);
    float4 rB1 = *(const float4*)(Wp + (size_t)8 * D_MODEL);
    {
        float4 h, l;
        split4(rA0, h, l);
        *(float4*)&sAh[aR0 * LDA + aC] = h;
        *(float4*)&sAl[aR0 * LDA + aC] = l;
        split4(rA1, h, l);
        *(float4*)&sAh[(aR0 + 64) * LDA + aC] = h;
        *(float4*)&sAl[(aR0 + 64) * LDA + aC] = l;
        split4(rB0, h, l);
        *(float4*)&sBh[bR0 * LDB + bC] = h;
        *(float4*)&sBl[bR0 * LDB + bC] = l;
        split4(rB1, h, l);
        *(float4*)&sBh[(bR0 + 8) * LDB + bC] = h;
        *(float4*)&sBl[(bR0 + 8) * LDB + bC] = l;
    }
    __syncthreads();

    const int NIT = D_MODEL / 16;
    for (int it = 0; it < NIT; it++) {
        float4 nA0, nA1, nB0, nB1;
        const bool nxt = (it + 1) < NIT;
        if (nxt) {
            const int k0 = (it + 1) * 16;
            nA0 = *(const float4*)(Ap + k0);
            nA1 = *(const float4*)(Ap + (size_t)64 * D_MODEL + k0);
            nB0 = *(const float4*)(Wp + (size_t)k0 * D_MODEL);
            nB1 = *(const float4*)(Wp + (size_t)(k0 + 8) * D_MODEL);
        }

#pragma unroll
        for (int ks = 0; ks < 2; ks++) {
            const int k0 = ks * 8;
            wmma::fragment<wmma::matrix_a, 16, 16, 8, wmma::precision::tf32,
                           wmma::row_major> ah[2], al[2];
            wmma::fragment<wmma::matrix_b, 16, 16, 8, wmma::precision::tf32,
                           wmma::row_major> bh[4], bl[4];
#pragma unroll
            for (int i = 0; i < 2; i++) {
                wmma::load_matrix_sync(ah[i], &sAh[(wm + i * 16) * LDA + k0], LDA);
                wmma::load_matrix_sync(al[i], &sAl[(wm + i * 16) * LDA + k0], LDA);
            }
#pragma unroll
            for (int j = 0; j < 4; j++) {
                wmma::load_matrix_sync(bh[j], &sBh[k0 * LDB + wn + j * 16], LDB);
                wmma::load_matrix_sync(bl[j], &sBl[k0 * LDB + wn + j * 16], LDB);
            }
#pragma unroll
            for (int i = 0; i < 2; i++)
#pragma unroll
                for (int j = 0; j < 4; j++) {
                    wmma::mma_sync(acc[i][j], ah[i], bh[j], acc[i][j]);
                    wmma::mma_sync(acc[i][j], al[i], bh[j], acc[i][j]);
                    wmma::mma_sync(acc[i][j], ah[i], bl[j], acc[i][j]);
                }
        }
        __syncthreads();

        if (nxt) {
            float4 h, l;
            split4(nA0, h, l);
            *(float4*)&sAh[aR0 * LDA + aC] = h;
            *(float4*)&sAl[aR0 * LDA + aC] = l;
            split4(nA1, h, l);
            *(float4*)&sAh[(aR0 + 64) * LDA + aC] = h;
            *(float4*)&sAl[(aR0 + 64) * LDA + aC] = l;
            split4(nB0, h, l);
            *(float4*)&sBh[bR0 * LDB + bC] = h;
            *(float4*)&sBl[bR0 * LDB + bC] = l;
            split4(nB1, h, l);
            *(float4*)&sBh[(bR0 + 8) * LDB + bC] = h;
            *(float4*)&sBl[(bR0 + 8) * LDB + bC] = l;
            __syncthreads();
        }
    }

    float* ep = sEp[warp];
    const int erow = lane >> 1;
    const int ec0  = (lane & 1) * 8;
#pragma unroll
    for (int i = 0; i < 2; i++)
#pragma unroll
        for (int j = 0; j < 4; j++) {
            wmma::store_matrix_sync(ep, acc[i][j], 20, wmma::mem_row_major);
            __syncwarp();
            const int gm = mbase + wm + i * 16 + erow;
            const int gn = nbase + wn + j * 16 + ec0;
            float4 v0 = *(float4*)&ep[erow * 20 + ec0];
            float4 v1 = *(float4*)&ep[erow * 20 + ec0 + 4];
            const float4 bb0 = *(const float4*)&bias[gn];
            const float4 bb1 = *(const float4*)&bias[gn + 4];
            v0.x += bb0.x; v0.y += bb0.y; v0.z += bb0.z; v0.w += bb0.w;
            v1.x += bb1.x; v1.y += bb1.y; v1.z += bb1.z; v1.w += bb1.w;
            *(float4*)&C[(size_t)gm * D_MODEL + gn]     = v0;
            *(float4*)&C[(size_t)gm * D_MODEL + gn + 4] = v1;
            __syncwarp();
        }
}

__global__ __launch_bounds__(256) void qkv_gemm_kernel(
    const float* __restrict__ q, const float* __restrict__ k,
    const float* __restrict__ v,
    const float* __restrict__ w_q, const float* __restrict__ b_q,
    const float* __restrict__ w_k, const float* __restrict__ b_k,
    const float* __restrict__ w_v, const float* __restrict__ b_v,
    float* __restrict__ Qp, float* __restrict__ Kp, float* __restrict__ Vp)
{
    const int z = blockIdx.z;
    const float* A    = (z == 0) ? q   : (z == 1) ? k   : v;
    const float* W    = (z == 0) ? w_q : (z == 1) ? w_k : w_v;
    const float* bias = (z == 0) ? b_q : (z == 1) ? b_k : b_v;
    float*       C    = (z == 0) ? Qp  : (z == 1) ? Kp  : Vp;
    gemm_bias_tc(A, W, bias, C);
}

__global__ __launch_bounds__(256) void gemm_bias_kernel(
    const float* __restrict__ A, const float* __restrict__ W,
    const float* __restrict__ bias, float* __restrict__ C)
{
    gemm_bias_tc(A, W, bias, C);
}

// ----------------------------------------------------------------------------
// Flash attention, Dh=64. S = QK^T on tensor cores (3xTF32 wmma, S -> smem);
// softmax / online-max / PV (fp32 FFMA) / O accumulation UNCHANGED from the
// passing fp32 kernel (they just read S from smem instead of registers).
// Dynamic smem layout (floats):
//   QH[64*68], QL[64*68], KH[64*68], KL[64*68], VS[64*64], SP[64*68]
// ----------------------------------------------------------------------------
#define LDQ 68
#define FLASH_SMEM_FLOATS (5 * 64 * LDQ + 64 * 64)
#define FLASH_SMEM_BYTES (FLASH_SMEM_FLOATS * 4)

__global__ __launch_bounds__(256, 2) void flash_attn_kernel(
    const float* __restrict__ Qg, const float* __restrict__ Kg,
    const float* __restrict__ Vg, float* __restrict__ Og)
{
    extern __shared__ float sm[];
    float* QH = sm;
    float* QL = QH + 64 * LDQ;
    float* KH = QL + 64 * LDQ;
    float* KL = KH + 64 * LDQ;
    float* VS = KL + 64 * LDQ;   // [j][d], stride 64
    float* SP = VS + 64 * 64;    // S then P, [i][j], stride LDQ

    const int qt = blockIdx.x;
    const int h  = blockIdx.y;
    const int b  = blockIdx.z;
    const int tid = threadIdx.x;
    const int tx = tid & 15;        // key / d-out microtile
    const int ty = tid >> 4;        // query-row microtile
    const int warp = tid >> 5;

    const size_t base = ((size_t)b * SEQ) * D_MODEL + (size_t)h * HEAD_DIM;
    const int qbase = qt * 64;

    const int kj  = tid & 63;       // row (key index j / query index i)
    const int kd0 = (tid >> 6) * 4; // col group
    const float* Kbase = Kg + base;
    const float* Vbase = Vg + base;

    // Load Q tile natural [i][d], pre-scaled by 1/8, split hi/lo
    {
        const float* qp = Qg + base + (size_t)(qbase + kj) * D_MODEL;
#pragma unroll
        for (int r = 0; r < 4; r++) {
            const int d = kd0 + r * 16;
            float4 vv = *(const float4*)(qp + d);
            float4 hi, lo;
            vv.x *= 0.125f; vv.y *= 0.125f; vv.z *= 0.125f; vv.w *= 0.125f;
            split4(vv, hi, lo);
            *(float4*)&QH[kj * LDQ + d] = hi;
            *(float4*)&QL[kj * LDQ + d] = lo;
        }
    }

    float acc[4][4];
    float mrow[4], lrow[4];
#pragma unroll
    for (int r = 0; r < 4; r++) {
        mrow[r] = -1e30f;
        lrow[r] = 0.0f;
#pragma unroll
        for (int c = 0; c < 4; c++) acc[r][c] = 0.0f;
    }

    // Prefetch registers for tile 0
    float4 kreg[4], vreg[4];
    {
        const float* kp = Kbase + (size_t)kj * D_MODEL;
#pragma unroll
        for (int r = 0; r < 4; r++)
            kreg[r] = *(const float4*)(kp + kd0 + r * 16);
#pragma unroll
        for (int it = 0; it < 4; it++) {
            const int s  = tid + it * 256;
            const int j2 = s >> 4;
            const int d4 = (s & 15) * 4;
            vreg[it] = *(const float4*)(Vbase + (size_t)j2 * D_MODEL + d4);
        }
    }

    // wmma tile assignment: warp -> 16x32 of S (2 tiles of 16x16)
    const int wRow = (warp >> 1) * 16;
    const int wCol = (warp & 1) * 32;

    const int NKV = SEQ / 64;
    for (int kvt = 0; kvt < NKV; kvt++) {
        __syncthreads();   // prior-iteration SP/VS reads complete (also Q init)

        // Store prefetched K (transposed, hi/lo split -> KH/KL [d][j]) and V
#pragma unroll
        for (int r = 0; r < 4; r++) {
            const int d = kd0 + r * 16;
            float4 hi, lo;
            split4(kreg[r], hi, lo);
            KH[(d + 0) * LDQ + kj] = hi.x;  KL[(d + 0) * LDQ + kj] = lo.x;
            KH[(d + 1) * LDQ + kj] = hi.y;  KL[(d + 1) * LDQ + kj] = lo.y;
            KH[(d + 2) * LDQ + kj] = hi.z;  KL[(d + 2) * LDQ + kj] = lo.z;
            KH[(d + 3) * LDQ + kj] = hi.w;  KL[(d + 3) * LDQ + kj] = lo.w;
        }
#pragma unroll
        for (int it = 0; it < 4; it++) {
            const int s  = tid + it * 256;
            const int j2 = s >> 4;
            const int d4 = (s & 15) * 4;
            *(float4*)&VS[j2 * 64 + d4] = vreg[it];
        }
        __syncthreads();

        // S = Q K^T via 3xTF32 wmma; each warp computes its 16x32 patch
        {
            wmma::fragment<wmma::accumulator, 16, 16, 8, float> sacc[2];
            wmma::fill_fragment(sacc[0], 0.0f);
            wmma::fill_fragment(sacc[1], 0.0f);
#pragma unroll
            for (int d0 = 0; d0 < 64; d0 += 8) {
                wmma::fragment<wmma::matrix_a, 16, 16, 8, wmma::precision::tf32,
                               wmma::row_major> ah, al;
                wmma::load_matrix_sync(ah, &QH[wRow * LDQ + d0], LDQ);
                wmma::load_matrix_sync(al, &QL[wRow * LDQ + d0], LDQ);
#pragma unroll
                for (int c = 0; c < 2; c++) {
                    wmma::fragment<wmma::matrix_b, 16, 16, 8, wmma::precision::tf32,
                                   wmma::row_major> bh, bl;
                    wmma::load_matrix_sync(bh, &KH[d0 * LDQ + wCol + c * 16], LDQ);
                    wmma::load_matrix_sync(bl, &KL[d0 * LDQ + wCol + c * 16], LDQ);
                    wmma::mma_sync(sacc[c], ah, bh, sacc[c]);
                    wmma::mma_sync(sacc[c], al, bh, sacc[c]);
                    wmma::mma_sync(sacc[c], ah, bl, sacc[c]);
                }
            }
            wmma::store_matrix_sync(&SP[wRow * LDQ + wCol],      sacc[0], LDQ,
                                    wmma::mem_row_major);
            wmma::store_matrix_sync(&SP[wRow * LDQ + wCol + 16], sacc[1], LDQ,
                                    wmma::mem_row_major);
        }

        // Issue next tile's global loads now; latency hides under softmax+PV.
        if (kvt + 1 < NKV) {
            const int kb = (kvt + 1) * 64;
            const float* kp = Kbase + (size_t)(kb + kj) * D_MODEL;
#pragma unroll
            for (int r = 0; r < 4; r++)
                kreg[r] = *(const float4*)(kp + kd0 + r * 16);
#pragma unroll
            for (int it = 0; it < 4; it++) {
                const int s  = tid + it * 256;
                const int j2 = s >> 4;
                const int d4 = (s & 15) * 4;
                vreg[it] = *(const float4*)(Vbase + (size_t)(kb + j2) * D_MODEL + d4);
            }
        }
        __syncthreads();   // all warps' S patches visible

        // Online softmax per row (reads its own 16 S values; in-place P write)
#pragma unroll
        for (int r = 0; r < 4; r++) {
            float4 s4 = *(float4*)&SP[(ty * 4 + r) * LDQ + tx * 4];
            float mx = fmaxf(fmaxf(s4.x, s4.y), fmaxf(s4.z, s4.w));
            mx = fmaxf(mx, __shfl_xor_sync(0xffffffffu, mx, 1));
            mx = fmaxf(mx, __shfl_xor_sync(0xffffffffu, mx, 2));
            mx = fmaxf(mx, __shfl_xor_sync(0xffffffffu, mx, 4));
            mx = fmaxf(mx, __shfl_xor_sync(0xffffffffu, mx, 8));
            const float mn = fmaxf(mrow[r], mx);
            const float corr = __expf(mrow[r] - mn);
            float p0 = __expf(s4.x - mn);
            float p1 = __expf(s4.y - mn);
            float p2 = __expf(s4.z - mn);
            float p3 = __expf(s4.w - mn);
            float sum = p0 + p1 + p2 + p3;
            sum += __shfl_xor_sync(0xffffffffu, sum, 1);
            sum += __shfl_xor_sync(0xffffffffu, sum, 2);
            sum += __shfl_xor_sync(0xffffffffu, sum, 4);
            sum += __shfl_xor_sync(0xffffffffu, sum, 8);
            lrow[r] = lrow[r] * corr + sum;
            mrow[r] = mn;
#pragma unroll
            for (int c = 0; c < 4; c++) acc[r][c] *= corr;
            *(float4*)&SP[(ty * 4 + r) * LDQ + tx * 4] = make_float4(p0, p1, p2, p3);
        }
        __syncthreads();

        // O += P V : rows ty*4+r, dims tx*4+c (fp32 FFMA, unchanged)
#pragma unroll 8
        for (int j = 0; j < 64; j++) {
            float4 v4 = *(const float4*)&VS[j * 64 + tx * 4];
#pragma unroll
            for (int r = 0; r < 4; r++) {
                const float pv = SP[(ty * 4 + r) * LDQ + j];   // broadcast load
                acc[r][0] += pv * v4.x;
                acc[r][1] += pv * v4.y;
                acc[r][2] += pv * v4.z;
                acc[r][3] += pv * v4.w;
            }
        }
    }

    // Epilogue: normalize and store
#pragma unroll
    for (int r = 0; r < 4; r++) {
        const float inv = 1.0f / lrow[r];
        float4 o;
        o.x = acc[r][0] * inv;
        o.y = acc[r][1] * inv;
        o.z = acc[r][2] * inv;
        o.w = acc[r][3] * inv;
        *(float4*)(Og + base + (size_t)(qbase + ty * 4 + r) * D_MODEL + tx * 4) = o;
    }
}

// ----------------------------------------------------------------------------
// Launch
// ----------------------------------------------------------------------------
extern "C" void kernel_launch(void* const* d_in, const int* in_sizes, int n_in,
                              void* d_out, int out_size)
{
    const float* q   = (const float*)d_in[0];
    const float* k   = (const float*)d_in[1];
    const float* v   = (const float*)d_in[2];
    const float* w_q = (const float*)d_in[3];
    const float* b_q = (const float*)d_in[4];
    const float* w_k = (const float*)d_in[5];
    const float* b_k = (const float*)d_in[6];
    const float* w_v = (const float*)d_in[7];
    const float* b_v = (const float*)d_in[8];
    const float* w_o = (const float*)d_in[9];
    const float* b_o = (const float*)d_in[10];
    float* out = (float*)d_out;

    const int BS = in_sizes[0] / D_MODEL;   // B * S
    const int B  = BS / SEQ;

    float *Qp, *Kp, *Vp, *AO;
    cudaGetSymbolAddress((void**)&Qp, g_Qp);
    cudaGetSymbolAddress((void**)&Kp, g_Kp);
    cudaGetSymbolAddress((void**)&Vp, g_Vp);
    cudaGetSymbolAddress((void**)&AO, g_AO);

    cudaFuncSetAttribute(flash_attn_kernel,
                         cudaFuncAttributeMaxDynamicSharedMemorySize,
                         FLASH_SMEM_BYTES);

    dim3 qkv_grid(D_MODEL / 128, BS / 128, 3);
    qkv_gemm_kernel<<<qkv_grid, 256>>>(q, k, v, w_q, b_q, w_k, b_k, w_v, b_v,
                                       Qp, Kp, Vp);

    dim3 attn_grid(SEQ / 64, NUM_HEADS, B);
    flash_attn_kernel<<<attn_grid, 256, FLASH_SMEM_BYTES>>>(Qp, Kp, Vp, AO);

    dim3 gemm_grid(D_MODEL / 128, BS / 128);
    gemm_bias_kernel<<<gemm_grid, 256>>>(AO, w_o, b_o, out);
}